// round 4
// baseline (speedup 1.0000x reference)
#include <cuda_runtime.h>

// Grouper: FPS (B=8, N=8192 -> S=2048) + KNN(K=32) grouping.
// Output layout assumed: [neighborhood (B,S,K,3) | centers (B,S,3)] flattened.

#define BB 8
#define NN 8192
#define SS 2048
#define KK 32
#define FPS_T 1024
#define PPT 8            // points per thread in FPS (NN / FPS_T)
#define KNN_T 256
#define KPT 32           // points per thread in KNN (NN / KNN_T)

typedef unsigned long long ull;

// Scratch: centers coordinates produced by FPS, consumed by KNN.
__device__ float g_centers[BB * SS * 3];

// ---------------------------------------------------------------------------
// FPS: one CTA per batch. All point coords live in registers (8 pts/thread);
// a shared-memory copy of xyz exists only so the reducing thread can broadcast
// the winner's coordinates. Bit-exact arithmetic: sub/mul/add in rn mode, no
// FMA contraction; argmax tie-break = lowest index (JAX argmax semantics)
// via 64-bit key = (dist_bits << 32) | ~idx  maximized.
// ---------------------------------------------------------------------------
__global__ __launch_bounds__(FPS_T, 1)
void fps_kernel(const float* __restrict__ xyz, float* __restrict__ dout,
                int write_centers) {
    extern __shared__ float sxyz[];            // 3*NN floats (96 KB)
    __shared__ ull warpKey[FPS_T / 32];
    __shared__ float scur[3];

    const int b    = blockIdx.x;
    const int tid  = threadIdx.x;
    const int lane = tid & 31;
    const int wid  = tid >> 5;
    const float* base = xyz + (size_t)b * NN * 3;

    // smem copy of this batch's points (for winner-coordinate lookup)
    for (int i = tid; i < 3 * NN; i += FPS_T) sxyz[i] = base[i];

    // register-resident coords + running min distance
    float px[PPT], py[PPT], pz[PPT], mind[PPT];
#pragma unroll
    for (int k = 0; k < PPT; ++k) {
        int j = tid + k * FPS_T;
        px[k] = base[3 * j + 0];
        py[k] = base[3 * j + 1];
        pz[k] = base[3 * j + 2];
        mind[k] = __int_as_float(0x7f800000);  // +inf
    }

    if (tid == 0) {
        // first selected index is always 0
        float x0 = base[0], y0 = base[1], z0 = base[2];
        scur[0] = x0; scur[1] = y0; scur[2] = z0;
        float* c = g_centers + (size_t)b * SS * 3;
        c[0] = x0; c[1] = y0; c[2] = z0;
        if (write_centers) {
            float* oc = dout + (size_t)BB * SS * KK * 3 + (size_t)b * SS * 3;
            oc[0] = x0; oc[1] = y0; oc[2] = z0;
        }
    }
    __syncthreads();

    for (int s = 1; s < SS; ++s) {
        const float cx = scur[0], cy = scur[1], cz = scur[2];
        float best = -1.0f;
        int bidx = 0;
#pragma unroll
        for (int k = 0; k < PPT; ++k) {
            float dx = __fadd_rn(px[k], -cx);
            float dy = __fadd_rn(py[k], -cy);
            float dz = __fadd_rn(pz[k], -cz);
            float d = __fadd_rn(__fadd_rn(__fmul_rn(dx, dx), __fmul_rn(dy, dy)),
                                __fmul_rn(dz, dz));
            float m = fminf(mind[k], d);
            mind[k] = m;
            // strict '>' with ascending k keeps the lowest index on ties
            if (m > best) { best = m; bidx = tid + (k << 10); }
        }
        // max distance, then min index: pack ~idx in low 32 bits, take max key
        ull key = ((ull)__float_as_uint(best) << 32) | (unsigned)(~bidx);
#pragma unroll
        for (int off = 16; off; off >>= 1) {
            ull o = __shfl_xor_sync(0xffffffffu, key, off);
            if (o > key) key = o;
        }
        if (lane == 0) warpKey[wid] = key;
        __syncthreads();                       // (A) also protects scur reads
        if (wid == 0) {
            ull k2 = warpKey[lane];            // exactly 32 warps
#pragma unroll
            for (int off = 16; off; off >>= 1) {
                ull o = __shfl_xor_sync(0xffffffffu, k2, off);
                if (o > k2) k2 = o;
            }
            if (lane == 0) {
                int widx = (int)(~(unsigned)k2);
                float wx = sxyz[3 * widx + 0];
                float wy = sxyz[3 * widx + 1];
                float wz = sxyz[3 * widx + 2];
                scur[0] = wx; scur[1] = wy; scur[2] = wz;
                float* c = g_centers + ((size_t)b * SS + s) * 3;
                c[0] = wx; c[1] = wy; c[2] = wz;
                if (write_centers) {
                    float* oc = dout + (size_t)BB * SS * KK * 3 +
                                ((size_t)b * SS + s) * 3;
                    oc[0] = wx; oc[1] = wy; oc[2] = wz;
                }
            }
        }
        __syncthreads();                       // (B)
    }
}

// ---------------------------------------------------------------------------
// KNN: one CTA (256 threads) per center. Distance bits stored as u32 in smem
// (point index is the slot position, so 64-bit keys are reconstructed on the
// fly: key = (bits<<32)|i, ascending == ascending distance then lower index
// == jax.lax.top_k order). 32 extract-min rounds; each thread caches the min
// over its own 32 strided slots so only the winning thread rescans per round.
// ---------------------------------------------------------------------------
__global__ __launch_bounds__(KNN_T)
void knn_kernel(const float* __restrict__ xyz, float* __restrict__ dout) {
    __shared__ unsigned keys[NN];              // 32 KB
    __shared__ ull wmin[KNN_T / 32];
    __shared__ ull bmin;
    __shared__ int sel[KK];

    const int cidx = blockIdx.x;               // b * SS + s
    const int b    = cidx >> 11;               // / 2048
    const int tid  = threadIdx.x;
    const int lane = tid & 31;
    const int wid  = tid >> 5;
    const float* base = xyz + (size_t)b * NN * 3;
    const float* c = g_centers + (size_t)cidx * 3;
    const float ncx = -c[0], ncy = -c[1], ncz = -c[2];

    // distances + per-thread cached minimum key
    ull myMin = ~0ull;
#pragma unroll
    for (int r = 0; r < KPT; ++r) {
        int i = tid + (r << 8);
        float dx = __fadd_rn(base[3 * i + 0], ncx);
        float dy = __fadd_rn(base[3 * i + 1], ncy);
        float dz = __fadd_rn(base[3 * i + 2], ncz);
        float d = __fadd_rn(__fadd_rn(__fmul_rn(dx, dx), __fmul_rn(dy, dy)),
                            __fmul_rn(dz, dz));
        unsigned bits = __float_as_uint(d);    // d >= 0 -> monotone as u32
        keys[i] = bits;
        ull v = ((ull)bits << 32) | (unsigned)i;
        if (v < myMin) myMin = v;
    }
    __syncthreads();

    for (int t = 0; t < KK; ++t) {
        ull k = myMin;
#pragma unroll
        for (int off = 16; off; off >>= 1) {
            ull o = __shfl_xor_sync(0xffffffffu, k, off);
            if (o < k) k = o;
        }
        if (lane == 0) wmin[wid] = k;
        __syncthreads();
        if (tid == 0) {
            ull m = wmin[0];
#pragma unroll
            for (int w = 1; w < KNN_T / 32; ++w)
                m = (wmin[w] < m) ? wmin[w] : m;
            bmin = m;
            sel[t] = (int)(unsigned)m;         // low 32 bits = point index
        }
        __syncthreads();
        if (myMin == bmin) {                   // unique owner (index in key)
            int pid = (int)(unsigned)myMin;
            keys[pid] = 0xFFFFFFFFu;           // invalidate (> any valid bits)
            ull mn = ~0ull;
#pragma unroll
            for (int r = 0; r < KPT; ++r) {
                int i = tid + (r << 8);
                ull v = ((ull)keys[i] << 32) | (unsigned)i;
                if (v < mn) mn = v;
            }
            myMin = mn;
        }
        // next round's first __syncthreads orders everything needed
    }
    __syncthreads();

    // write the 32 re-centered neighbors (order = ascending distance)
    if (tid < KK) {
        int pid = sel[tid];
        float x = base[3 * pid + 0];
        float y = base[3 * pid + 1];
        float z = base[3 * pid + 2];
        float* o = dout + ((size_t)cidx * KK + tid) * 3;
        o[0] = __fadd_rn(x, ncx);
        o[1] = __fadd_rn(y, ncy);
        o[2] = __fadd_rn(z, ncz);
    }
}

// ---------------------------------------------------------------------------

extern "C" void kernel_launch(void* const* d_in, const int* in_sizes, int n_in,
                              void* d_out, int out_size) {
    (void)in_sizes; (void)n_in;
    const float* xyz = (const float*)d_in[0];
    float* out = (float*)d_out;

    // If the harness output is only the neighborhood, skip the centers tail.
    const int full = BB * SS * KK * 3 + BB * SS * 3;
    int write_centers = (out_size >= full) ? 1 : 0;

    const int fps_smem = 3 * NN * (int)sizeof(float);  // 96 KB dynamic
    cudaFuncSetAttribute(fps_kernel,
                         cudaFuncAttributeMaxDynamicSharedMemorySize, fps_smem);

    fps_kernel<<<BB, FPS_T, fps_smem>>>(xyz, out, write_centers);
    knn_kernel<<<BB * SS, KNN_T>>>(xyz, out);
}

// round 7
// speedup vs baseline: 1.1590x; 1.1590x over previous
#include <cuda_runtime.h>

// Grouper: FPS (B=8, N=8192 -> S=2048) + KNN(K=32) grouping.
// Output layout: [neighborhood (B,S,K,3) | centers (B,S,3)] flattened.
//
// All distance math is scalar __fadd_rn/__fmul_rn (no FMA contraction, no
// packed f32x2 — R5 showed the packed path is NOT bit-identical here), in
// the reference's ((dx^2+dy^2)+dz^2) evaluation order. All selections use
// 64-bit keys reproducing JAX first-occurrence (lowest-index) tie-breaking.

#define BB 8
#define NN 8192
#define SS 2048
#define KK 32

#define FPS_T 512
#define FPP   16              // points per thread (NN / FPS_T)
#define FW    (FPS_T / 32)    // 16 warps

#define KNN_T 256
#define KW    (KNN_T / 32)    // 8 warps
#define KPT   32              // points per thread (NN / KNN_T)

typedef unsigned long long ull;

// Scratch: centers coordinates produced by FPS, consumed by KNN.
__device__ float g_centers[BB * SS * 3];

__device__ __forceinline__ ull warp_max_u64(ull k) {
#pragma unroll
    for (int off = 16; off; off >>= 1) {
        ull o = __shfl_xor_sync(0xffffffffu, k, off);
        if (o > k) k = o;
    }
    return k;
}
__device__ __forceinline__ ull warp_min_u64(ull k) {
#pragma unroll
    for (int off = 16; off; off >>= 1) {
        ull o = __shfl_xor_sync(0xffffffffu, k, off);
        if (o < k) k = o;
    }
    return k;
}

// ---------------------------------------------------------------------------
// FPS: one CTA per batch, 512 threads x 16 points in registers.
// Argmax tie-break = lowest index (64-bit key = dist_bits<<32 | ~idx, max).
// One __syncthreads per step: double-buffered warpKey + every warp performs
// the second-level reduce redundantly (no serial tail, no second barrier).
// ---------------------------------------------------------------------------
__global__ __launch_bounds__(FPS_T, 1)
void fps_kernel(const float* __restrict__ xyz) {
    extern __shared__ float sxyz[];            // 3*NN floats (96 KB)
    __shared__ ull warpKey[2][FW];

    const int b    = blockIdx.x;
    const int tid  = threadIdx.x;
    const int lane = tid & 31;
    const int wid  = tid >> 5;
    const float* base = xyz + (size_t)b * NN * 3;

    // smem copy of this batch's points (winner-coordinate lookup)
    for (int i = tid; i < 3 * NN; i += FPS_T) sxyz[i] = base[i];
    __syncthreads();

    // register-resident coords + running min distance
    float px[FPP], py[FPP], pz[FPP], mind[FPP];
#pragma unroll
    for (int k = 0; k < FPP; ++k) {
        int j = tid + k * FPS_T;
        px[k] = sxyz[3 * j + 0];
        py[k] = sxyz[3 * j + 1];
        pz[k] = sxyz[3 * j + 2];
        mind[k] = __int_as_float(0x7f800000);  // +inf
    }

    if (tid == 0) {                            // first selected index is 0
        float* c = g_centers + (size_t)b * SS * 3;
        c[0] = sxyz[0]; c[1] = sxyz[1]; c[2] = sxyz[2];
    }

    int widx = 0;                              // current center index (uniform)
    for (int s = 1; s < SS; ++s) {
        const int p = s & 1;
        const float cx = sxyz[3 * widx + 0];
        const float cy = sxyz[3 * widx + 1];
        const float cz = sxyz[3 * widx + 2];

        float best = -__int_as_float(0x7f800000);
#pragma unroll
        for (int k = 0; k < FPP; ++k) {
            float dx = __fadd_rn(px[k], -cx);
            float dy = __fadd_rn(py[k], -cy);
            float dz = __fadd_rn(pz[k], -cz);
            float d = __fadd_rn(__fadd_rn(__fmul_rn(dx, dx), __fmul_rn(dy, dy)),
                                __fmul_rn(dz, dz));
            float m = fminf(mind[k], d);
            mind[k] = m;
            best = fmaxf(best, m);
        }
        // deferred argmax: descending k so the lowest k (lowest index) wins
        int bidx = 0;
#pragma unroll
        for (int k = FPP - 1; k >= 0; --k)
            if (mind[k] == best) bidx = tid + (k << 9);

        ull key = ((ull)__float_as_uint(best) << 32) | (unsigned)(~bidx);
        key = warp_max_u64(key);
        if (lane == 0) warpKey[p][wid] = key;
        __syncthreads();                       // the only barrier per step

        // all warps redundantly reduce the 16 warp keys
        ull k2 = warpKey[p][lane & (FW - 1)];
#pragma unroll
        for (int off = FW / 2; off; off >>= 1) {
            ull o = __shfl_xor_sync(0xffffffffu, k2, off);
            if (o > k2) k2 = o;
        }
        widx = (int)(~(unsigned)k2);

        if (tid == 0) {
            float* c = g_centers + ((size_t)b * SS + s) * 3;
            c[0] = sxyz[3 * widx + 0];
            c[1] = sxyz[3 * widx + 1];
            c[2] = sxyz[3 * widx + 2];
        }
        // no second barrier: double-buffered warpKey; sxyz is read-only here
    }
}

// ---------------------------------------------------------------------------
// KNN: one CTA (256 threads) per center. Distance bits as u32 in smem (index
// = slot). 32 extract-min rounds, ONE barrier per round (double-buffered
// wmin + redundant 8-value reduce); warp-level min cached in a register and
// recomputed only by the warp that owned the extracted point.
// ---------------------------------------------------------------------------
__global__ __launch_bounds__(KNN_T)
void knn_kernel(const float* __restrict__ xyz, float* __restrict__ dout,
                int write_centers) {
    __shared__ unsigned keys[NN];              // 32 KB
    __shared__ ull wmin[2][KW];
    __shared__ int sel[KK];

    const int cidx = blockIdx.x;               // b * SS + s
    const int b    = cidx >> 11;
    const int tid  = threadIdx.x;
    const int lane = tid & 31;
    const int wid  = tid >> 5;
    const float* base = xyz + (size_t)b * NN * 3;
    const float* c = g_centers + (size_t)cidx * 3;
    const float ncx = -c[0], ncy = -c[1], ncz = -c[2];

    // distances + per-thread cached minimum key
    ull myMin = ~0ull;
#pragma unroll
    for (int r = 0; r < KPT; ++r) {
        int i = tid + (r << 8);
        float dx = __fadd_rn(base[3 * i + 0], ncx);
        float dy = __fadd_rn(base[3 * i + 1], ncy);
        float dz = __fadd_rn(base[3 * i + 2], ncz);
        float d = __fadd_rn(__fadd_rn(__fmul_rn(dx, dx), __fmul_rn(dy, dy)),
                            __fmul_rn(dz, dz));
        unsigned bits = __float_as_uint(d);    // d >= 0 -> monotone as u32
        keys[i] = bits;
        ull v = ((ull)bits << 32) | (unsigned)i;
        if (v < myMin) myMin = v;
    }
    __syncthreads();

    ull wkey = warp_min_u64(myMin);            // cached per-warp minimum

    for (int t = 0; t < KK; ++t) {
        const int p = t & 1;
        if (lane == 0) wmin[p][wid] = wkey;
        __syncthreads();                       // the only barrier per round

        ull m = wmin[p][lane & (KW - 1)];
#pragma unroll
        for (int off = KW / 2; off; off >>= 1) {
            ull o = __shfl_xor_sync(0xffffffffu, m, off);
            if (o < m) m = o;
        }                                      // m = block min (all threads)
        const int opid = (int)(unsigned)m;     // winning point index
        if (tid == 0) sel[t] = opid;

        if (myMin == m) {                      // unique owner thread
            keys[opid] = 0xFFFFFFFFu;          // invalidate
            ull mn = ~0ull;
#pragma unroll
            for (int r = 0; r < KPT; ++r) {
                int i = tid + (r << 8);
                ull v = ((ull)keys[i] << 32) | (unsigned)i;
                if (v < mn) mn = v;
            }
            myMin = mn;
        }
        if (((opid & (KNN_T - 1)) >> 5) == wid)  // only owner warp re-reduces
            wkey = warp_min_u64(myMin);
    }
    __syncthreads();

    // write the 32 re-centered neighbors (order = ascending distance)
    if (tid < KK) {
        int pid = sel[tid];
        float* o = dout + ((size_t)cidx * KK + tid) * 3;
        o[0] = __fadd_rn(base[3 * pid + 0], ncx);
        o[1] = __fadd_rn(base[3 * pid + 1], ncy);
        o[2] = __fadd_rn(base[3 * pid + 2], ncz);
    } else if (write_centers && tid < KK + 3) {
        int comp = tid - KK;
        dout[(size_t)BB * SS * KK * 3 + (size_t)cidx * 3 + comp] = c[comp];
    }
}

// ---------------------------------------------------------------------------

extern "C" void kernel_launch(void* const* d_in, const int* in_sizes, int n_in,
                              void* d_out, int out_size) {
    (void)in_sizes; (void)n_in;
    const float* xyz = (const float*)d_in[0];
    float* out = (float*)d_out;

    const int full = BB * SS * KK * 3 + BB * SS * 3;
    int write_centers = (out_size >= full) ? 1 : 0;

    const int fps_smem = 3 * NN * (int)sizeof(float);  // 96 KB dynamic
    cudaFuncSetAttribute(fps_kernel,
                         cudaFuncAttributeMaxDynamicSharedMemorySize, fps_smem);

    fps_kernel<<<BB, FPS_T, fps_smem>>>(xyz);
    knn_kernel<<<BB * SS, KNN_T>>>(xyz, out, write_centers);
}